// round 3
// baseline (speedup 1.0000x reference)
#include <cuda_runtime.h>

// Problem constants (fixed by setup_inputs): B=8, N=2048, D=256, HEAD=8, ATT=32
#define NROWS 16384   // B*N
#define DMODEL 256

// Scratch (allocation-free rule: device globals)
__device__ __align__(16) float g_Q[NROWS * DMODEL];
__device__ __align__(16) float g_K[NROWS * DMODEL];
__device__ __align__(16) float g_V[NROWS * DMODEL];
__device__ __align__(16) float g_AO[NROWS * DMODEL];

// ---------------------------------------------------------------------------
// C[M,256] = A[M,256] @ W[256,256]^T + bias   (torch Linear convention)
// Tiles: 64x64 output, K-step 32. 16x16 threads, 4x4 per-thread micro-tile.
// Smem stored k-major (As[k][m], Ws[k][n]) so compute-phase LDS.128 is
// conflict-free and vectorized.
// ---------------------------------------------------------------------------
__global__ __launch_bounds__(256)
void gemm_bias_kernel(const float* __restrict__ A,
                      const float* __restrict__ W,
                      const float* __restrict__ bias,
                      float* __restrict__ C)
{
    __shared__ __align__(16) float As[32][64];
    __shared__ __align__(16) float Ws[32][64];

    const int tx = threadIdx.x, ty = threadIdx.y;
    const int tid = ty * 16 + tx;
    const int m0 = blockIdx.y * 64;
    const int n0 = blockIdx.x * 64;

    float acc[4][4] = {};

    for (int kk = 0; kk < 256; kk += 32) {
        #pragma unroll
        for (int it = 0; it < 2; it++) {
            int idx = tid * 2 + it;          // 0..511
            int r   = idx >> 3;              // 0..63
            int c4  = (idx & 7) * 4;         // 0,4,..,28
            float4 va = *(const float4*)(A + (size_t)(m0 + r) * 256 + kk + c4);
            As[c4 + 0][r] = va.x; As[c4 + 1][r] = va.y;
            As[c4 + 2][r] = va.z; As[c4 + 3][r] = va.w;
            float4 vw = *(const float4*)(W + (size_t)(n0 + r) * 256 + kk + c4);
            Ws[c4 + 0][r] = vw.x; Ws[c4 + 1][r] = vw.y;
            Ws[c4 + 2][r] = vw.z; Ws[c4 + 3][r] = vw.w;
        }
        __syncthreads();
        #pragma unroll
        for (int k = 0; k < 32; k++) {
            float4 a = *(const float4*)&As[k][ty * 4];
            float4 b = *(const float4*)&Ws[k][tx * 4];
            acc[0][0] += a.x*b.x; acc[0][1] += a.x*b.y; acc[0][2] += a.x*b.z; acc[0][3] += a.x*b.w;
            acc[1][0] += a.y*b.x; acc[1][1] += a.y*b.y; acc[1][2] += a.y*b.z; acc[1][3] += a.y*b.w;
            acc[2][0] += a.z*b.x; acc[2][1] += a.z*b.y; acc[2][2] += a.z*b.z; acc[2][3] += a.z*b.w;
            acc[3][0] += a.w*b.x; acc[3][1] += a.w*b.y; acc[3][2] += a.w*b.z; acc[3][3] += a.w*b.w;
        }
        __syncthreads();
    }

    float4 bv = *(const float4*)(bias + n0 + tx * 4);
    #pragma unroll
    for (int i = 0; i < 4; i++) {
        float4 r4;
        r4.x = acc[i][0] + bv.x;
        r4.y = acc[i][1] + bv.y;
        r4.z = acc[i][2] + bv.z;
        r4.w = acc[i][3] + bv.w;
        *(float4*)(C + (size_t)(m0 + ty * 4 + i) * 256 + n0 + tx * 4) = r4;
    }
}

// ---------------------------------------------------------------------------
// Causal flash attention, fp32. One block = one (head,batch) x 64-row Q tile.
// Head h of sequence b lives at column offset h*32 inside the [B,N,256]
// projection buffers (identical to the reference's split-heads view).
// Q/K in k-major smem (conflict-free S-GEMM); V row-major; P staged in smem.
// ---------------------------------------------------------------------------
__global__ __launch_bounds__(256)
void attn_kernel(const float* __restrict__ Qg, const float* __restrict__ Kg,
                 const float* __restrict__ Vg, float* __restrict__ Og)
{
    __shared__ __align__(16) float Qs[32][64];   // [k][row]
    __shared__ __align__(16) float Ks[32][64];   // [k][col]
    __shared__ __align__(16) float Vs[64][32];   // [n][d]
    __shared__ __align__(16) float Ps[64][64];   // [row][n]
    __shared__ float m_s[64];
    __shared__ float l_s[64];

    const int tx = threadIdx.x, ty = threadIdx.y;
    const int tid = ty * 16 + tx;
    const int tq = (int)gridDim.x - 1 - (int)blockIdx.x;  // long blocks first
    const int hb = blockIdx.y;
    const int h  = hb & 7;
    const int bb = hb >> 3;
    const size_t base = (size_t)bb * 2048 * 256 + (size_t)h * 32;
    const float* Qb = Qg + base;
    const float* Kb = Kg + base;
    const float* Vb = Vg + base;
    float*       Ob = Og + base;

    const float scale = 0.17677669529663687f;   // 1/sqrt(32), folded into Q

    #pragma unroll
    for (int it = 0; it < 2; it++) {
        int idx = tid * 2 + it;
        int r   = idx >> 3;
        int c4  = (idx & 7) * 4;
        float4 v = *(const float4*)(Qb + (size_t)(tq * 64 + r) * 256 + c4);
        Qs[c4 + 0][r] = v.x * scale; Qs[c4 + 1][r] = v.y * scale;
        Qs[c4 + 2][r] = v.z * scale; Qs[c4 + 3][r] = v.w * scale;
    }
    if (tid < 64) { m_s[tid] = -1e30f; l_s[tid] = 0.0f; }

    const int r0 = ty * 4;   // S/O rows owned by this thread
    const int c0 = tx * 4;   // S cols owned
    const int cc = tx * 2;   // O cols owned
    float o[4][2] = {};

    for (int j = 0; j <= tq; j++) {
        __syncthreads();     // prev PV done; Ks/Vs/Ps reusable
        #pragma unroll
        for (int it = 0; it < 2; it++) {
            int idx = tid * 2 + it;
            int r   = idx >> 3;
            int c4  = (idx & 7) * 4;
            float4 kv = *(const float4*)(Kb + (size_t)(j * 64 + r) * 256 + c4);
            Ks[c4 + 0][r] = kv.x; Ks[c4 + 1][r] = kv.y;
            Ks[c4 + 2][r] = kv.z; Ks[c4 + 3][r] = kv.w;
            float4 vv = *(const float4*)(Vb + (size_t)(j * 64 + r) * 256 + c4);
            *(float4*)&Vs[r][c4] = vv;
        }
        __syncthreads();

        // S = (Q*scale) @ K^T : per-thread 4x4
        float s[4][4] = {};
        #pragma unroll
        for (int k = 0; k < 32; k++) {
            float4 a = *(const float4*)&Qs[k][r0];
            float4 b = *(const float4*)&Ks[k][c0];
            s[0][0] += a.x*b.x; s[0][1] += a.x*b.y; s[0][2] += a.x*b.z; s[0][3] += a.x*b.w;
            s[1][0] += a.y*b.x; s[1][1] += a.y*b.y; s[1][2] += a.y*b.z; s[1][3] += a.y*b.w;
            s[2][0] += a.z*b.x; s[2][1] += a.z*b.y; s[2][2] += a.z*b.z; s[2][3] += a.z*b.w;
            s[3][0] += a.w*b.x; s[3][1] += a.w*b.y; s[3][2] += a.w*b.z; s[3][3] += a.w*b.w;
        }

        if (j == tq) {  // causal mask only on diagonal tile
            #pragma unroll
            for (int i = 0; i < 4; i++)
                #pragma unroll
                for (int jj = 0; jj < 4; jj++)
                    if (c0 + jj > r0 + i) s[i][jj] = -1e30f;
        }

        float mold[4], lold[4];
        #pragma unroll
        for (int i = 0; i < 4; i++) { mold[i] = m_s[r0 + i]; lold[i] = l_s[r0 + i]; }
        __syncwarp();   // all reads of old stats before any lane rewrites them

        float alpha[4];
        #pragma unroll
        for (int i = 0; i < 4; i++) {
            // row max across the 16 lanes sharing this row (lanes 0-15 / 16-31)
            float mt = fmaxf(fmaxf(s[i][0], s[i][1]), fmaxf(s[i][2], s[i][3]));
            mt = fmaxf(mt, __shfl_xor_sync(0xffffffffu, mt, 1));
            mt = fmaxf(mt, __shfl_xor_sync(0xffffffffu, mt, 2));
            mt = fmaxf(mt, __shfl_xor_sync(0xffffffffu, mt, 4));
            mt = fmaxf(mt, __shfl_xor_sync(0xffffffffu, mt, 8));
            float mnew = fmaxf(mold[i], mt);
            alpha[i] = __expf(mold[i] - mnew);
            s[i][0] = __expf(s[i][0] - mnew);
            s[i][1] = __expf(s[i][1] - mnew);
            s[i][2] = __expf(s[i][2] - mnew);
            s[i][3] = __expf(s[i][3] - mnew);
            float ls = s[i][0] + s[i][1] + s[i][2] + s[i][3];
            ls += __shfl_xor_sync(0xffffffffu, ls, 1);
            ls += __shfl_xor_sync(0xffffffffu, ls, 2);
            ls += __shfl_xor_sync(0xffffffffu, ls, 4);
            ls += __shfl_xor_sync(0xffffffffu, ls, 8);
            m_s[r0 + i] = mnew;                    // identical value from all lanes
            l_s[r0 + i] = lold[i] * alpha[i] + ls;
            o[i][0] *= alpha[i];
            o[i][1] *= alpha[i];
            float4 pv = make_float4(s[i][0], s[i][1], s[i][2], s[i][3]);
            *(float4*)&Ps[r0 + i][c0] = pv;
        }
        __syncthreads();   // Ps fully written

        // O += P @ V : each thread owns rows r0..r0+3, cols cc..cc+1
        #pragma unroll
        for (int n4 = 0; n4 < 64; n4 += 4) {
            float4 p0 = *(const float4*)&Ps[r0 + 0][n4];
            float4 p1 = *(const float4*)&Ps[r0 + 1][n4];
            float4 p2 = *(const float4*)&Ps[r0 + 2][n4];
            float4 p3 = *(const float4*)&Ps[r0 + 3][n4];
            float2 v0 = *(const float2*)&Vs[n4 + 0][cc];
            float2 v1 = *(const float2*)&Vs[n4 + 1][cc];
            float2 v2 = *(const float2*)&Vs[n4 + 2][cc];
            float2 v3 = *(const float2*)&Vs[n4 + 3][cc];
            o[0][0] += p0.x*v0.x + p0.y*v1.x + p0.z*v2.x + p0.w*v3.x;
            o[0][1] += p0.x*v0.y + p0.y*v1.y + p0.z*v2.y + p0.w*v3.y;
            o[1][0] += p1.x*v0.x + p1.y*v1.x + p1.z*v2.x + p1.w*v3.x;
            o[1][1] += p1.x*v0.y + p1.y*v1.y + p1.z*v2.y + p1.w*v3.y;
            o[2][0] += p2.x*v0.x + p2.y*v1.x + p2.z*v2.x + p2.w*v3.x;
            o[2][1] += p2.x*v0.y + p2.y*v1.y + p2.z*v2.y + p2.w*v3.y;
            o[3][0] += p3.x*v0.x + p3.y*v1.x + p3.z*v2.x + p3.w*v3.x;
            o[3][1] += p3.x*v0.y + p3.y*v1.y + p3.z*v2.y + p3.w*v3.y;
        }
    }

    #pragma unroll
    for (int i = 0; i < 4; i++) {
        float inv = 1.0f / l_s[r0 + i];   // own lanes wrote it; identical values
        float2 res = make_float2(o[i][0] * inv, o[i][1] * inv);
        *(float2*)(Ob + (size_t)(tq * 64 + r0 + i) * 256 + cc) = res;
    }
}

// ---------------------------------------------------------------------------
extern "C" void kernel_launch(void* const* d_in, const int* in_sizes, int n_in,
                              void* d_out, int out_size)
{
    const float* query = (const float*)d_in[0];
    const float* key   = (const float*)d_in[1];
    const float* value = (const float*)d_in[2];
    const float* Wq    = (const float*)d_in[3];
    const float* bq    = (const float*)d_in[4];
    const float* Wk    = (const float*)d_in[5];
    const float* bk    = (const float*)d_in[6];
    const float* Wv    = (const float*)d_in[7];
    const float* bv    = (const float*)d_in[8];
    const float* Wo    = (const float*)d_in[9];
    const float* bo    = (const float*)d_in[10];
    float* out = (float*)d_out;

    float *Q, *K, *V, *AO;
    cudaGetSymbolAddress((void**)&Q,  g_Q);
    cudaGetSymbolAddress((void**)&K,  g_K);
    cudaGetSymbolAddress((void**)&V,  g_V);
    cudaGetSymbolAddress((void**)&AO, g_AO);

    dim3 blk(16, 16);
    dim3 gproj(DMODEL / 64, NROWS / 64);   // (4, 256)

    gemm_bias_kernel<<<gproj, blk>>>(query, Wq, bq, Q);
    gemm_bias_kernel<<<gproj, blk>>>(key,   Wk, bk, K);
    gemm_bias_kernel<<<gproj, blk>>>(value, Wv, bv, V);

    attn_kernel<<<dim3(2048 / 64, 64), blk>>>(Q, K, V, AO);

    gemm_bias_kernel<<<gproj, blk>>>(AO, Wo, bo, out);
}